// round 12
// baseline (speedup 1.0000x reference)
#include <cuda_runtime.h>
#include <cuda_bf16.h>
#include <stdint.h>
#include <math.h>

#define N_NODES 100000
#define N_EDGES 800000
#define HD      128            // hidden dim H
#define K1      256            // H + IN
#define FF      512            // 4*H
#define INV_SCALE (1.0f/30.0f)
#define LN_EPS  1e-5f

#define ET 128                 // edges per tile (edge kernel)
#define N_TILES (N_EDGES / ET) // 6250
#define NODE_TILES ((N_NODES + 127) / 128)   // 782

// ---------------------------------------------------------------------------
// device globals (no cudaMalloc allowed)
// ---------------------------------------------------------------------------
__device__ float          g_dh[(size_t)N_NODES * HD];
__device__ __nv_bfloat16  g_WT1[HD * K1];   // W1^T  [n=128][k=256] bf16
__device__ __nv_bfloat16  g_WT2[HD * HD];   // W2^T  [128][128] bf16
__device__ __nv_bfloat16  g_WT3[HD * HD];   // W3^T  [128][128] bf16
__device__ __nv_bfloat16  g_D1Th[FF * HD];  // D1^T hi  [512][128]
__device__ __nv_bfloat16  g_D1Tl[FF * HD];  // D1^T lo
__device__ __nv_bfloat16  g_D2Th[HD * FF];  // D2^T hi  [128][512]
__device__ __nv_bfloat16  g_D2Tl[HD * FF];  // D2^T lo

// ---------------------------------------------------------------------------
// EDGE kernel SMEM layout (bytes)
// ---------------------------------------------------------------------------
#define AS1   528
#define WS1   528
#define WS2   272
#define OFF_A    0
#define OFF_W1   67584
#define OFF_W2   135168
#define OFF_W3   169984
#define OFF_B1   204800
#define OFF_B2   205312
#define OFF_B3   205824
#define OFF_SRC  206336        // 2 x 512B (double-buffered src indices)
#define SMEM_TOTAL 207360

// ---------------------------------------------------------------------------
// NODE kernel SMEM layout (bytes)
// ---------------------------------------------------------------------------
#define NS2 272
#define NOFF_XH  0
#define NOFF_XL  34816
#define NOFF_HH  69632
#define NOFF_HL  104448
#define NOFF_W   139264       // weight chunk hi(+0)/lo(+34816); reused fp32 stage
#define NOFF_DB1 208896
#define NOFF_DB2 210944
#define NOFF_G1  211456
#define NOFF_BE1 211968
#define NOFF_G2  212480
#define NOFF_BE2 212992
#define NOFF_ST  213504       // stats float2 [128][4] = 4096
#define NSMEM_TOTAL 217600

// ---------------------------------------------------------------------------
// PTX helpers — ONLY non-'a' instructions
// ---------------------------------------------------------------------------
__device__ __forceinline__ uint32_t smem_u32(const void* p) {
    uint32_t a;
    asm("{ .reg .u64 t; cvta.to.shared.u64 t, %1; cvt.u32.u64 %0, t; }" : "=r"(a) : "l"(p));
    return a;
}
__device__ __forceinline__ void ldsm_x4(uint32_t addr, uint32_t& r0, uint32_t& r1,
                                        uint32_t& r2, uint32_t& r3) {
    asm volatile("ldmatrix.sync.aligned.m8n8.x4.shared.b16 {%0,%1,%2,%3}, [%4];"
                 : "=r"(r0), "=r"(r1), "=r"(r2), "=r"(r3) : "r"(addr));
}
__device__ __forceinline__ void mma_16816(float c[4], uint32_t a0, uint32_t a1,
                                          uint32_t a2, uint32_t a3,
                                          uint32_t b0, uint32_t b1) {
    asm volatile("mma.sync.aligned.m16n8k16.row.col.f32.bf16.bf16.f32 "
                 "{%0,%1,%2,%3}, {%4,%5,%6,%7}, {%8,%9}, {%0,%1,%2,%3};"
                 : "+f"(c[0]), "+f"(c[1]), "+f"(c[2]), "+f"(c[3])
                 : "r"(a0), "r"(a1), "r"(a2), "r"(a3), "r"(b0), "r"(b1));
}
__device__ __forceinline__ uint32_t pk2(float lo, float hi) {
    uint32_t r;
    asm("cvt.rn.bf16x2.f32 %0, %1, %2;" : "=r"(r) : "f"(hi), "f"(lo));
    return r;
}
__device__ __forceinline__ float bflo(uint32_t u) {
    __nv_bfloat162 t = *reinterpret_cast<__nv_bfloat162*>(&u);
    return __bfloat162float(t.x);
}
__device__ __forceinline__ float bfhi(uint32_t u) {
    __nv_bfloat162 t = *reinterpret_cast<__nv_bfloat162*>(&u);
    return __bfloat162float(t.y);
}
__device__ __forceinline__ void split2(float a, float b, uint32_t& h, uint32_t& l) {
    h = pk2(a, b);
    l = pk2(a - bflo(h), b - bfhi(h));
}
__device__ __forceinline__ void red_add_v4(float* p, float a, float b, float c, float d) {
    asm volatile("red.global.add.v4.f32 [%0], {%1, %2, %3, %4};"
                 :: "l"(p), "f"(a), "f"(b), "f"(c), "f"(d) : "memory");
}

// ---------------------------------------------------------------------------
// single-bf16 MLP layer (edge, 16 warps): warp (mw, nw) owns rows mw*32..+31,
// cols nw*32..+31. acc[2][4][4].
// ---------------------------------------------------------------------------
template <int KSTEPS, int ASTRIDE, int WSTRIDE>
__device__ __forceinline__ void mlp_layer(uint32_t sb, int Aoff, int Woff,
                                          int lane, int mw, int nw,
                                          float acc[2][4][4]) {
#pragma unroll
    for (int i = 0; i < 2; i++)
#pragma unroll
        for (int j = 0; j < 4; j++)
#pragma unroll
            for (int q = 0; q < 4; q++) acc[i][j][q] = 0.f;

    const uint32_t aBase = sb + Aoff + (mw * 32 + (lane & 15)) * ASTRIDE + ((lane >> 4) << 4);
    const uint32_t bBase = sb + Woff
        + (nw * 32 + (lane & 7) + ((lane >> 4) << 3)) * WSTRIDE
        + (((lane >> 3) & 1) << 4);

#pragma unroll
    for (int ks = 0; ks < KSTEPS; ks++) {
        const int k0b = ks * 32;
        uint32_t a0, a1, a2, a3, a4, a5, a6, a7;
        ldsm_x4(aBase + k0b, a0, a1, a2, a3);
        ldsm_x4(aBase + 16 * ASTRIDE + k0b, a4, a5, a6, a7);
#pragma unroll
        for (int p = 0; p < 2; p++) {
            uint32_t b0, b1, b2, b3;
            ldsm_x4(bBase + p * 16 * WSTRIDE + k0b, b0, b1, b2, b3);
            mma_16816(acc[0][2 * p],     a0, a1, a2, a3, b0, b1);
            mma_16816(acc[1][2 * p],     a4, a5, a6, a7, b0, b1);
            mma_16816(acc[0][2 * p + 1], a0, a1, a2, a3, b2, b3);
            mma_16816(acc[1][2 * p + 1], a4, a5, a6, a7, b2, b3);
        }
    }
}

// split (hi/lo) MLP layer (node, 16 warps): acc (+)= Ah@Wh + Ah@Wl + Al@Wh
template <int KSTEPS, bool CLEAR>
__device__ __forceinline__ void mlp_layer_split(uint32_t sb, int AHoff, int ALoff,
                                                int WHoff, int WLoff,
                                                int lane, int mw, int nw,
                                                float acc[2][4][4]) {
    if (CLEAR) {
#pragma unroll
        for (int i = 0; i < 2; i++)
#pragma unroll
            for (int j = 0; j < 4; j++)
#pragma unroll
                for (int q = 0; q < 4; q++) acc[i][j][q] = 0.f;
    }
    const uint32_t rb = (mw * 32 + (lane & 15)) * NS2 + ((lane >> 4) << 4);
    const uint32_t ahB = sb + AHoff + rb;
    const uint32_t alB = sb + ALoff + rb;
    const uint32_t wb = (nw * 32 + (lane & 7) + ((lane >> 4) << 3)) * NS2
                      + (((lane >> 3) & 1) << 4);
    const uint32_t whB = sb + WHoff + wb;
    const uint32_t wlB = sb + WLoff + wb;

#pragma unroll
    for (int ks = 0; ks < KSTEPS; ks++) {
        const int k0b = ks * 32;
        uint32_t h0, h1, h2, h3, h4, h5, h6, h7;
        uint32_t l0, l1, l2, l3, l4, l5, l6, l7;
        ldsm_x4(ahB + k0b, h0, h1, h2, h3);
        ldsm_x4(ahB + 16 * NS2 + k0b, h4, h5, h6, h7);
        ldsm_x4(alB + k0b, l0, l1, l2, l3);
        ldsm_x4(alB + 16 * NS2 + k0b, l4, l5, l6, l7);
#pragma unroll
        for (int p = 0; p < 2; p++) {
            uint32_t wh0, wh1, wh2, wh3, wl0, wl1, wl2, wl3;
            ldsm_x4(whB + p * 16 * NS2 + k0b, wh0, wh1, wh2, wh3);
            ldsm_x4(wlB + p * 16 * NS2 + k0b, wl0, wl1, wl2, wl3);
            mma_16816(acc[0][2 * p], h0, h1, h2, h3, wh0, wh1);
            mma_16816(acc[0][2 * p], h0, h1, h2, h3, wl0, wl1);
            mma_16816(acc[0][2 * p], l0, l1, l2, l3, wh0, wh1);
            mma_16816(acc[1][2 * p], h4, h5, h6, h7, wh0, wh1);
            mma_16816(acc[1][2 * p], h4, h5, h6, h7, wl0, wl1);
            mma_16816(acc[1][2 * p], l4, l5, l6, l7, wh0, wh1);
            mma_16816(acc[0][2 * p + 1], h0, h1, h2, h3, wh2, wh3);
            mma_16816(acc[0][2 * p + 1], h0, h1, h2, h3, wl2, wl3);
            mma_16816(acc[0][2 * p + 1], l0, l1, l2, l3, wh2, wh3);
            mma_16816(acc[1][2 * p + 1], h4, h5, h6, h7, wh2, wh3);
            mma_16816(acc[1][2 * p + 1], h4, h5, h6, h7, wl2, wl3);
            mma_16816(acc[1][2 * p + 1], l4, l5, l6, l7, wh2, wh3);
        }
    }
}

// bias + relu -> bf16, write into edge A/mid region (stride AS1)
__device__ __forceinline__ void epi_relu_pack(char* smem, const float* bias,
                                              int lane, int mw, int nw,
                                              float acc[2][4][4]) {
#pragma unroll
    for (int i = 0; i < 2; i++) {
        const int r = mw * 32 + i * 16 + (lane >> 2);
#pragma unroll
        for (int j = 0; j < 4; j++) {
            const int c = nw * 32 + j * 8 + (lane & 3) * 2;
            const float bc0 = bias[c], bc1 = bias[c + 1];
            float f0 = fmaxf(acc[i][j][0] + bc0, 0.f);
            float f1 = fmaxf(acc[i][j][1] + bc1, 0.f);
            float f2 = fmaxf(acc[i][j][2] + bc0, 0.f);
            float f3 = fmaxf(acc[i][j][3] + bc1, 0.f);
            *reinterpret_cast<uint32_t*>(smem + OFF_A + r * AS1 + c * 2)       = pk2(f0, f1);
            *reinterpret_cast<uint32_t*>(smem + OFF_A + (r + 8) * AS1 + c * 2) = pk2(f2, f3);
        }
    }
}

// ---------------------------------------------------------------------------
// prep: transpose + bf16-convert all weights
// ---------------------------------------------------------------------------
__global__ void prep_weights_kernel(const float* __restrict__ W1,
                                    const float* __restrict__ W2,
                                    const float* __restrict__ W3,
                                    const float* __restrict__ D1,
                                    const float* __restrict__ D2) {
    int n = blockIdx.x;
    int t = threadIdx.x;
    {
        float v = D1[t * FF + n];
        __nv_bfloat16 h = __float2bfloat16(v);
        g_D1Th[n * HD + t] = h;
        g_D1Tl[n * HD + t] = __float2bfloat16(v - __bfloat162float(h));
    }
    if (n < HD) {
        for (int k = t; k < K1; k += blockDim.x)
            g_WT1[n * K1 + k] = __float2bfloat16(W1[k * HD + n]);
        for (int k = t; k < HD; k += blockDim.x) {
            g_WT2[n * HD + k] = __float2bfloat16(W2[k * HD + n]);
            g_WT3[n * HD + k] = __float2bfloat16(W3[k * HD + n]);
        }
        for (int k = t; k < FF; k += blockDim.x) {
            float v = D2[k * HD + n];
            __nv_bfloat16 h = __float2bfloat16(v);
            g_D2Th[n * FF + k] = h;
            g_D2Tl[n * FF + k] = __float2bfloat16(v - __bfloat162float(h));
        }
    }
}

__global__ void zero_dh_kernel() {
    size_t n4 = (size_t)N_NODES * HD / 4;
    float4 z = make_float4(0.f, 0.f, 0.f, 0.f);
    float4* p = reinterpret_cast<float4*>(g_dh);
    for (size_t i = (size_t)blockIdx.x * blockDim.x + threadIdx.x; i < n4;
         i += (size_t)gridDim.x * blockDim.x)
        p[i] = z;
}

// ---------------------------------------------------------------------------
// Edge MLP. Persistent: grid=148, 512 threads (16 warps).
// ---------------------------------------------------------------------------
__global__ void __launch_bounds__(512, 1)
edge_hmma_kernel(const float* __restrict__ hE,
                 const int* __restrict__ eidx,
                 const float* __restrict__ b1,
                 const float* __restrict__ b2,
                 const float* __restrict__ b3) {
    extern __shared__ char smem[];
    const uint32_t sb = smem_u32(smem);
    const int tid  = threadIdx.x;
    const int wid  = tid >> 5;
    const int lane = tid & 31;
    const int mw   = wid & 3;          // row strip
    const int nw   = wid >> 2;         // col slice 0..3 (32 cols)

    // ---- stage weights ------------------------------------------------------
    {
        const uint4* w1g = reinterpret_cast<const uint4*>(g_WT1);
#pragma unroll
        for (int i = 0; i < 8; i++) {
            int idx = i * 512 + tid; int n = idx >> 5, ch = idx & 31;
            *reinterpret_cast<uint4*>(smem + OFF_W1 + n * WS1 + ch * 16) = w1g[n * 32 + ch];
        }
        const uint4* w2g = reinterpret_cast<const uint4*>(g_WT2);
        const uint4* w3g = reinterpret_cast<const uint4*>(g_WT3);
#pragma unroll
        for (int i = 0; i < 4; i++) {
            int idx = i * 512 + tid; int n = idx >> 4, ch = idx & 15;
            *reinterpret_cast<uint4*>(smem + OFF_W2 + n * WS2 + ch * 16) = w2g[n * 16 + ch];
            *reinterpret_cast<uint4*>(smem + OFF_W3 + n * WS2 + ch * 16) = w3g[n * 16 + ch];
        }
        if (tid < 128) {
            ((float*)(smem + OFF_B1))[tid] = b1[tid];
            ((float*)(smem + OFF_B2))[tid] = b2[tid];
            ((float*)(smem + OFF_B3))[tid] = b3[tid];
        }
    }

    const float* bias1 = (const float*)(smem + OFF_B1);
    const float* bias2 = (const float*)(smem + OFF_B2);
    const float* bias3 = (const float*)(smem + OFF_B3);
    int* srcArr = (int*)(smem + OFF_SRC);

    // ---- stage first tile ---------------------------------------------------
    {
        const int e0 = blockIdx.x * ET;
        const float4* gE4 = reinterpret_cast<const float4*>(hE) + (size_t)e0 * 64;
#pragma unroll
        for (int i = 0; i < 8; i++) {
            int idx = i * 512 + tid; int r = idx >> 5, ch = idx & 31;
            float4 fa = gE4[(size_t)r * 64 + ch * 2];
            float4 fb = gE4[(size_t)r * 64 + ch * 2 + 1];
            uint4 u;
            u.x = pk2(fa.x, fa.y); u.y = pk2(fa.z, fa.w);
            u.z = pk2(fb.x, fb.y); u.w = pk2(fb.z, fb.w);
            *reinterpret_cast<uint4*>(smem + OFF_A + r * AS1 + ch * 16) = u;
        }
        if (tid < 128) srcArr[tid] = eidx[e0 + tid];
    }
    __syncthreads();

    float acc[2][4][4];
    int buf = 0;

    for (int tile = blockIdx.x; tile < N_TILES; tile += gridDim.x) {
        mlp_layer<16, AS1, WS1>(sb, OFF_A, OFF_W1, lane, mw, nw, acc);
        __syncthreads();
        epi_relu_pack(smem, bias1, lane, mw, nw, acc);
        __syncthreads();

        mlp_layer<8, AS1, WS2>(sb, OFF_A, OFF_W2, lane, mw, nw, acc);
        __syncthreads();
        epi_relu_pack(smem, bias2, lane, mw, nw, acc);
        __syncthreads();

        mlp_layer<8, AS1, WS2>(sb, OFF_A, OFF_W3, lane, mw, nw, acc);
        __syncthreads();        // A region + srcArr[buf] free

        // ---- prefetch next tile (overlaps scatter) --------------------------
        const int ntile = tile + (int)gridDim.x;
        if (ntile < N_TILES) {
            const int e0 = ntile * ET;
            const float4* gE4 = reinterpret_cast<const float4*>(hE) + (size_t)e0 * 64;
#pragma unroll
            for (int i = 0; i < 8; i++) {
                int idx = i * 512 + tid; int r = idx >> 5, ch = idx & 31;
                float4 fa = gE4[(size_t)r * 64 + ch * 2];
                float4 fb = gE4[(size_t)r * 64 + ch * 2 + 1];
                uint4 u;
                u.x = pk2(fa.x, fa.y); u.y = pk2(fa.z, fa.w);
                u.z = pk2(fb.x, fb.y); u.w = pk2(fb.z, fb.w);
                *reinterpret_cast<uint4*>(smem + OFF_A + r * AS1 + ch * 16) = u;
            }
            if (tid < 128) srcArr[(buf ^ 1) * 128 + tid] = eidx[e0 + tid];
        }

        // ---- register-direct scatter ----------------------------------------
        {
            const bool even = (lane & 1) == 0;
            const int cbase = nw * 32 + ((lane >> 1) & 1) * 4;
            const int r0a   = mw * 32 + (lane >> 2) + (even ? 0 : 8);
            const int src0  = srcArr[buf * 128 + r0a];
            const int src1  = srcArr[buf * 128 + r0a + 16];
#pragma unroll
            for (int i = 0; i < 2; i++) {
                float* dst = g_dh + (size_t)(i ? src1 : src0) * HD;
#pragma unroll
                for (int j = 0; j < 4; j++) {
                    const int c = nw * 32 + j * 8 + (lane & 3) * 2;
                    float v0 = (acc[i][j][0] + bias3[c])     * INV_SCALE;
                    float v1 = (acc[i][j][1] + bias3[c + 1]) * INV_SCALE;
                    float v2 = (acc[i][j][2] + bias3[c])     * INV_SCALE;
                    float v3 = (acc[i][j][3] + bias3[c + 1]) * INV_SCALE;
                    float o0 = __shfl_xor_sync(0xffffffffu, v0, 1);
                    float o1 = __shfl_xor_sync(0xffffffffu, v1, 1);
                    float o2 = __shfl_xor_sync(0xffffffffu, v2, 1);
                    float o3 = __shfl_xor_sync(0xffffffffu, v3, 1);
                    if (even) red_add_v4(dst + cbase + j * 8, v0, v1, o0, o1);
                    else      red_add_v4(dst + cbase + j * 8, o2, o3, v2, v3);
                }
            }
        }
        __syncthreads();
        buf ^= 1;
    }
}

// ---------------------------------------------------------------------------
// Node update on split-bf16 HMMA. grid=782, 512 threads (16 warps).
// ---------------------------------------------------------------------------
__global__ void __launch_bounds__(512, 1)
node_mma_kernel(const float* __restrict__ hV,
                const float* __restrict__ db1g, const float* __restrict__ db2g,
                const float* __restrict__ g1g,  const float* __restrict__ be1g,
                const float* __restrict__ g2g,  const float* __restrict__ be2g,
                float* __restrict__ out) {
    extern __shared__ char smem[];
    const uint32_t sb = smem_u32(smem);
    const int tid  = threadIdx.x;
    const int lane = tid & 31;
    const int wid  = tid >> 5;
    const int mw   = wid & 3;
    const int nw   = wid >> 2;         // 0..3
    const int n0   = blockIdx.x * 128;

    float* s_db1 = (float*)(smem + NOFF_DB1);
    float* s_db2 = (float*)(smem + NOFF_DB2);
    float* s_g1  = (float*)(smem + NOFF_G1);
    float* s_be1 = (float*)(smem + NOFF_BE1);
    float* s_g2  = (float*)(smem + NOFF_G2);
    float* s_be2 = (float*)(smem + NOFF_BE2);
    float2* s_st = (float2*)(smem + NOFF_ST);

    // non-exclusive staging: tid<512 covers db1; tid<128 also stages the rest
    s_db1[tid] = db1g[tid];
    if (tid < 128) {
        s_db2[tid] = db2g[tid];
        s_g1[tid]  = g1g[tid];  s_be1[tid] = be1g[tid];
        s_g2[tid]  = g2g[tid];  s_be2[tid] = be2g[tid];
    }

    // ---- phase 1: x = hV + dh ; LN1 ; split hi/lo (4 lanes per row) ---------
    {
        const int row     = tid >> 2;           // 0..127
        const int quarter = tid & 3;            // 32 floats each
        const int grow = min(n0 + row, N_NODES - 1);
        const float4* xv = reinterpret_cast<const float4*>(hV   + (size_t)grow * HD + quarter * 32);
        const float4* dv = reinterpret_cast<const float4*>(g_dh + (size_t)grow * HD + quarter * 32);
        float sum = 0.f, sq = 0.f;
        char* stage = smem + NOFF_W + row * 528 + quarter * 128;
#pragma unroll
        for (int i = 0; i < 8; i++) {
            float4 a = xv[i], b = dv[i];
            a.x += b.x; a.y += b.y; a.z += b.z; a.w += b.w;
            *reinterpret_cast<float4*>(stage + i * 16) = a;
            sum += a.x + a.y + a.z + a.w;
            sq  += a.x * a.x + a.y * a.y + a.z * a.z + a.w * a.w;
        }
        sum += __shfl_xor_sync(0xffffffffu, sum, 1);
        sq  += __shfl_xor_sync(0xffffffffu, sq, 1);
        sum += __shfl_xor_sync(0xffffffffu, sum, 2);
        sq  += __shfl_xor_sync(0xffffffffu, sq, 2);
        const float mean = sum * (1.f / HD);
        const float var  = sq * (1.f / HD) - mean * mean;
        const float rstd = rsqrtf(var + LN_EPS);
        __syncthreads();                 // params staged
#pragma unroll
        for (int i = 0; i < 8; i++) {
            float4 a = *reinterpret_cast<float4*>(stage + i * 16);
            const int c0 = quarter * 32 + i * 4;
            float h0 = (a.x - mean) * rstd * s_g1[c0 + 0] + s_be1[c0 + 0];
            float h1 = (a.y - mean) * rstd * s_g1[c0 + 1] + s_be1[c0 + 1];
            float h2 = (a.z - mean) * rstd * s_g1[c0 + 2] + s_be1[c0 + 2];
            float h3 = (a.w - mean) * rstd * s_g1[c0 + 3] + s_be1[c0 + 3];
            uint32_t ha, la, hb, lb;
            split2(h0, h1, ha, la);
            split2(h2, h3, hb, lb);
            *reinterpret_cast<uint2*>(smem + NOFF_XH + row * NS2 + c0 * 2) = make_uint2(ha, hb);
            *reinterpret_cast<uint2*>(smem + NOFF_XL + row * NS2 + c0 * 2) = make_uint2(la, lb);
        }
    }
    __syncthreads();

    // ---- phase 2: FFN over 4 hidden chunks ----------------------------------
    float acc2[2][4][4];
#pragma unroll
    for (int i = 0; i < 2; i++)
#pragma unroll
        for (int j = 0; j < 4; j++)
#pragma unroll
            for (int q = 0; q < 4; q++) acc2[i][j][q] = 0.f;

    for (int c = 0; c < 4; c++) {
        {
            const uint4* d1h = reinterpret_cast<const uint4*>(g_D1Th);
            const uint4* d1l = reinterpret_cast<const uint4*>(g_D1Tl);
#pragma unroll
            for (int it = 0; it < 4; it++) {
                int idx = it * 512 + tid; int n = idx >> 4, ch = idx & 15;
                int gidx = (c * 128 + n) * 16 + ch;
                *reinterpret_cast<uint4*>(smem + NOFF_W + n * NS2 + ch * 16)         = d1h[gidx];
                *reinterpret_cast<uint4*>(smem + NOFF_W + 34816 + n * NS2 + ch * 16) = d1l[gidx];
            }
        }
        __syncthreads();

        float acc1[2][4][4];
        mlp_layer_split<8, true>(sb, NOFF_XH, NOFF_XL, NOFF_W, NOFF_W + 34816,
                                 lane, mw, nw, acc1);

#pragma unroll
        for (int i = 0; i < 2; i++) {
            const int r = mw * 32 + i * 16 + (lane >> 2);
#pragma unroll
            for (int j = 0; j < 4; j++) {
                const int cc = nw * 32 + j * 8 + (lane & 3) * 2;
                const float b0 = s_db1[c * 128 + cc], b1 = s_db1[c * 128 + cc + 1];
                float f0 = fmaxf(acc1[i][j][0] + b0, 0.f);
                float f1 = fmaxf(acc1[i][j][1] + b1, 0.f);
                float f2 = fmaxf(acc1[i][j][2] + b0, 0.f);
                float f3 = fmaxf(acc1[i][j][3] + b1, 0.f);
                uint32_t h01, l01, h23, l23;
                split2(f0, f1, h01, l01);
                split2(f2, f3, h23, l23);
                *reinterpret_cast<uint32_t*>(smem + NOFF_HH + r * NS2 + cc * 2)       = h01;
                *reinterpret_cast<uint32_t*>(smem + NOFF_HL + r * NS2 + cc * 2)       = l01;
                *reinterpret_cast<uint32_t*>(smem + NOFF_HH + (r + 8) * NS2 + cc * 2) = h23;
                *reinterpret_cast<uint32_t*>(smem + NOFF_HL + (r + 8) * NS2 + cc * 2) = l23;
            }
        }
        __syncthreads();

        {
            const uint4* d2h = reinterpret_cast<const uint4*>(g_D2Th);
            const uint4* d2l = reinterpret_cast<const uint4*>(g_D2Tl);
#pragma unroll
            for (int it = 0; it < 4; it++) {
                int idx = it * 512 + tid; int n = idx >> 4, ch = idx & 15;
                int gidx = n * 64 + c * 16 + ch;
                *reinterpret_cast<uint4*>(smem + NOFF_W + n * NS2 + ch * 16)         = d2h[gidx];
                *reinterpret_cast<uint4*>(smem + NOFF_W + 34816 + n * NS2 + ch * 16) = d2l[gidx];
            }
        }
        __syncthreads();

        mlp_layer_split<8, false>(sb, NOFF_HH, NOFF_HL, NOFF_W, NOFF_W + 34816,
                                  lane, mw, nw, acc2);
        __syncthreads();
    }

    // ---- phase 3: residual + db2, LN2, store --------------------------------
    float sums[2][2], sqs[2][2];
#pragma unroll
    for (int i = 0; i < 2; i++) { sums[i][0] = sums[i][1] = 0.f; sqs[i][0] = sqs[i][1] = 0.f; }

#pragma unroll
    for (int i = 0; i < 2; i++) {
        const int r = mw * 32 + i * 16 + (lane >> 2);
#pragma unroll
        for (int j = 0; j < 4; j++) {
            const int cc = nw * 32 + j * 8 + (lane & 3) * 2;
            const uint32_t off = r * NS2 + cc * 2;
            uint32_t xh0 = *reinterpret_cast<uint32_t*>(smem + NOFF_XH + off);
            uint32_t xl0 = *reinterpret_cast<uint32_t*>(smem + NOFF_XL + off);
            uint32_t xh1 = *reinterpret_cast<uint32_t*>(smem + NOFF_XH + off + 8 * NS2);
            uint32_t xl1 = *reinterpret_cast<uint32_t*>(smem + NOFF_XL + off + 8 * NS2);
            float v0 = acc2[i][j][0] + s_db2[cc]     + bflo(xh0) + bflo(xl0);
            float v1 = acc2[i][j][1] + s_db2[cc + 1] + bfhi(xh0) + bfhi(xl0);
            float v2 = acc2[i][j][2] + s_db2[cc]     + bflo(xh1) + bflo(xl1);
            float v3 = acc2[i][j][3] + s_db2[cc + 1] + bfhi(xh1) + bfhi(xl1);
            acc2[i][j][0] = v0; acc2[i][j][1] = v1; acc2[i][j][2] = v2; acc2[i][j][3] = v3;
            sums[i][0] += v0 + v1;           sqs[i][0] += v0 * v0 + v1 * v1;
            sums[i][1] += v2 + v3;           sqs[i][1] += v2 * v2 + v3 * v3;
        }
    }
#pragma unroll
    for (int i = 0; i < 2; i++)
#pragma unroll
        for (int qh = 0; qh < 2; qh++) {
            float s = sums[i][qh], q = sqs[i][qh];
            s += __shfl_xor_sync(0xffffffffu, s, 1);
            q += __shfl_xor_sync(0xffffffffu, q, 1);
            s += __shfl_xor_sync(0xffffffffu, s, 2);
            q += __shfl_xor_sync(0xffffffffu, q, 2);
            sums[i][qh] = s; sqs[i][qh] = q;
        }
    if ((lane & 3) == 0) {
#pragma unroll
        for (int i = 0; i < 2; i++)
#pragma unroll
            for (int qh = 0; qh < 2; qh++) {
                const int r = mw * 32 + i * 16 + qh * 8 + (lane >> 2);
                s_st[r * 4 + nw] = make_float2(sums[i][qh], sqs[i][qh]);
            }
    }
    __syncthreads();

#pragma unroll
    for (int i = 0; i < 2; i++) {
#pragma unroll
        for (int qh = 0; qh < 2; qh++) {
            const int r = mw * 32 + i * 16 + qh * 8 + (lane >> 2);
            float2 A = s_st[r * 4 + 0], B = s_st[r * 4 + 1];
            float2 C = s_st[r * 4 + 2], D = s_st[r * 4 + 3];
            float S = A.x + B.x + C.x + D.x, Q = A.y + B.y + C.y + D.y;
            float mean = S * (1.f / HD);
            float var  = Q * (1.f / HD) - mean * mean;
            float rstd = rsqrtf(var + LN_EPS);
#pragma unroll
            for (int j = 0; j < 4; j++) {
                const int cc = nw * 32 + j * 8 + (lane & 3) * 2;
                float v0 = acc2[i][j][qh * 2 + 0];
                float v1 = acc2[i][j][qh * 2 + 1];
                float2 o;
                o.x = (v0 - mean) * rstd * s_g2[cc]     + s_be2[cc];
                o.y = (v1 - mean) * rstd * s_g2[cc + 1] + s_be2[cc + 1];
                *reinterpret_cast<float2*>(smem + NOFF_W + r * 528 + cc * 4) = o;
            }
        }
    }
    __syncthreads();

#pragma unroll
    for (int it = 0; it < 8; it++) {
        int idx = it * 512 + tid; int r = idx >> 5, c4 = idx & 31;
        if (n0 + r < N_NODES) {
            float4 v = *reinterpret_cast<float4*>(smem + NOFF_W + r * 528 + c4 * 16);
            *reinterpret_cast<float4*>(out + (size_t)(n0 + r) * HD + c4 * 4) = v;
        }
    }
}

// ---------------------------------------------------------------------------
extern "C" void kernel_launch(void* const* d_in, const int* in_sizes, int n_in,
                              void* d_out, int out_size) {
    const float* hV    = (const float*)d_in[0];
    const float* hE    = (const float*)d_in[1];
    const int*   eidx  = (const int*)d_in[2];
    const float* W1    = (const float*)d_in[3];
    const float* b1    = (const float*)d_in[4];
    const float* W2    = (const float*)d_in[5];
    const float* b2    = (const float*)d_in[6];
    const float* W3    = (const float*)d_in[7];
    const float* b3    = (const float*)d_in[8];
    const float* D1    = (const float*)d_in[9];
    const float* db1   = (const float*)d_in[10];
    const float* D2    = (const float*)d_in[11];
    const float* db2   = (const float*)d_in[12];
    const float* g1    = (const float*)d_in[13];
    const float* beta1 = (const float*)d_in[14];
    const float* g2    = (const float*)d_in[15];
    const float* beta2 = (const float*)d_in[16];
    float*       out   = (float*)d_out;

    static int attr_set = 0;
    if (!attr_set) {
        cudaFuncSetAttribute(edge_hmma_kernel,
                             cudaFuncAttributeMaxDynamicSharedMemorySize, SMEM_TOTAL);
        cudaFuncSetAttribute(node_mma_kernel,
                             cudaFuncAttributeMaxDynamicSharedMemorySize, NSMEM_TOTAL);
        attr_set = 1;
    }

    prep_weights_kernel<<<512, 128>>>(W1, W2, W3, D1, D2);
    zero_dh_kernel<<<1024, 256>>>();
    edge_hmma_kernel<<<148, 512, SMEM_TOTAL>>>(hE, eidx, b1, b2, b3);
    node_mma_kernel<<<NODE_TILES, 512, NSMEM_TOTAL>>>(hV, db1, db2,
                                                      g1, beta1, g2, beta2, out);
}